// round 11
// baseline (speedup 1.0000x reference)
#include <cuda_runtime.h>
#include <stdint.h>

// XNOR binarized linear, warp-broadcast popc (R5 champion structure) with:
//  - lane owns 8 CONSECUTIVE output cols -> 2x STG.128 per row (was 8x STG.32)
//  - 4+4 group split with immediate stores (lower live-register peak)
//  - __launch_bounds__(128,5): 20 warps/SM
// y[n,o] = (256 - 2*popc(xbits[n] ^ wbits[o])) * scale[o]

constexpr int NROWS = 262144;
constexpr int DIM   = 256;   // IN == OUT
constexpr int WPR   = 8;     // packed words per row

constexpr int CHUNK_ROWS = 128;                 // rows per block chunk (4 warps x 32)
constexpr int NCHUNK     = NROWS / CHUNK_ROWS;  // 2048
constexpr int GRID       = 740;                 // 148 SMs x 5 blocks

__device__ uint32_t g_wbits[DIM * WPR];

// ---------------------------------------------------------------------------
// Pre-kernel: pack weight sign bits (one warp per output row).
// Word (h*4+c), bit L  <->  element h*128 + 4L + c. Matches x packing below.
// ---------------------------------------------------------------------------
__global__ void pack_w_kernel(const float* __restrict__ w) {
    int warp = (blockIdx.x * blockDim.x + threadIdx.x) >> 5;
    int lane = threadIdx.x & 31;
    if (warp >= DIM) return;
    const float4* row = reinterpret_cast<const float4*>(w) + (size_t)warp * (DIM / 4);
#pragma unroll
    for (int h = 0; h < 2; ++h) {
        float4 v = row[h * 32 + lane];
        uint32_t m0 = __ballot_sync(0xFFFFFFFFu, v.x < 0.0f);
        uint32_t m1 = __ballot_sync(0xFFFFFFFFu, v.y < 0.0f);
        uint32_t m2 = __ballot_sync(0xFFFFFFFFu, v.z < 0.0f);
        uint32_t m3 = __ballot_sync(0xFFFFFFFFu, v.w < 0.0f);
        if (lane == 0) {
            *reinterpret_cast<uint4*>(&g_wbits[warp * WPR + h * 4]) =
                make_uint4(m0, m1, m2, m3);
        }
    }
}

// ---------------------------------------------------------------------------
// Main kernel: 128 threads (4 warps), grid-stride over 128-row chunks.
// Lane L computes output cols 8L..8L+7 for all of its warp's rows.
// ---------------------------------------------------------------------------
__global__ void __launch_bounds__(128, 5)
xnor_v2_kernel(const float* __restrict__ x,
               const float* __restrict__ scale,
               float* __restrict__ out) {
    const int warp = threadIdx.x >> 5;
    const int lane = threadIdx.x & 31;
    const int o0   = lane * 8;                  // first of 8 consecutive cols

    // Hoist weights (8 consecutive w rows = 256B per lane) + scales.
    uint4 wa[8], wb[8];
#pragma unroll
    for (int j = 0; j < 8; ++j) {
        wa[j] = *reinterpret_cast<const uint4*>(&g_wbits[(o0 + j) * WPR]);
        wb[j] = *reinterpret_cast<const uint4*>(&g_wbits[(o0 + j) * WPR + 4]);
    }
    const float4 S0 = *reinterpret_cast<const float4*>(scale + o0);
    const float4 S1 = *reinterpret_cast<const float4*>(scale + o0 + 4);

    constexpr uint32_t MAGIC256 = 0x4B400000u + 256u;   // 2^23*1.5 + 256

    const float4* x4 = reinterpret_cast<const float4*>(x);

    for (int ch = blockIdx.x; ch < NCHUNK; ch += gridDim.x) {
        const int row0 = ch * CHUNK_ROWS + warp * 32;
        const float4* rp = x4 + (size_t)row0 * (DIM / 4);
        float* orow = out + (size_t)row0 * DIM + o0;

        // prefetch first row
        float4 c0 = rp[lane];
        float4 c1 = rp[32 + lane];

#pragma unroll 2
        for (int r = 0; r < 32; ++r) {
            // prefetch next row (clamped on last iteration)
            const float4* np = rp + (size_t)(r + 1 < 32 ? r + 1 : r) * (DIM / 4);
            float4 n0 = np[lane];
            float4 n1 = np[32 + lane];

            // transpose row signs into 8 words, broadcast to all lanes
            uint32_t b0 = __ballot_sync(0xFFFFFFFFu, c0.x < 0.0f);
            uint32_t b1 = __ballot_sync(0xFFFFFFFFu, c0.y < 0.0f);
            uint32_t b2 = __ballot_sync(0xFFFFFFFFu, c0.z < 0.0f);
            uint32_t b3 = __ballot_sync(0xFFFFFFFFu, c0.w < 0.0f);
            uint32_t b4 = __ballot_sync(0xFFFFFFFFu, c1.x < 0.0f);
            uint32_t b5 = __ballot_sync(0xFFFFFFFFu, c1.y < 0.0f);
            uint32_t b6 = __ballot_sync(0xFFFFFFFFu, c1.z < 0.0f);
            uint32_t b7 = __ballot_sync(0xFFFFFFFFu, c1.w < 0.0f);

            // first 4 columns -> one STG.128
            {
                float y[4];
#pragma unroll
                for (int j = 0; j < 4; ++j) {
                    int p = __popc(b0 ^ wa[j].x) + __popc(b1 ^ wa[j].y) +
                            __popc(b2 ^ wa[j].z) + __popc(b3 ^ wa[j].w) +
                            __popc(b4 ^ wb[j].x) + __popc(b5 ^ wb[j].y) +
                            __popc(b6 ^ wb[j].z) + __popc(b7 ^ wb[j].w);
                    uint32_t t = MAGIC256 - 2u * (uint32_t)p;      // IMAD
                    y[j] = __uint_as_float(t) - 12582912.0f;       // exact int
                }
                float4 v = make_float4(y[0] * S0.x, y[1] * S0.y,
                                       y[2] * S0.z, y[3] * S0.w);
                *reinterpret_cast<float4*>(orow) = v;
            }
            // last 4 columns -> one STG.128
            {
                float y[4];
#pragma unroll
                for (int j = 0; j < 4; ++j) {
                    int p = __popc(b0 ^ wa[j + 4].x) + __popc(b1 ^ wa[j + 4].y) +
                            __popc(b2 ^ wa[j + 4].z) + __popc(b3 ^ wa[j + 4].w) +
                            __popc(b4 ^ wb[j + 4].x) + __popc(b5 ^ wb[j + 4].y) +
                            __popc(b6 ^ wb[j + 4].z) + __popc(b7 ^ wb[j + 4].w);
                    uint32_t t = MAGIC256 - 2u * (uint32_t)p;
                    y[j] = __uint_as_float(t) - 12582912.0f;
                }
                float4 v = make_float4(y[0] * S1.x, y[1] * S1.y,
                                       y[2] * S1.z, y[3] * S1.w);
                *reinterpret_cast<float4*>(orow + 4) = v;
            }

            c0 = n0; c1 = n1;
            orow += DIM;
        }
    }
}

// ---------------------------------------------------------------------------
// kernel_launch: d_in[0]=x [N,256] f32, d_in[1]=weight [256,256] f32,
//                d_in[2]=scale [1,256] f32; d_out = y [N,256] f32.
// ---------------------------------------------------------------------------
extern "C" void kernel_launch(void* const* d_in, const int* in_sizes, int n_in,
                              void* d_out, int out_size) {
    const float* x      = (const float*)d_in[0];
    const float* weight = (const float*)d_in[1];
    const float* scale  = (const float*)d_in[2];
    float* out          = (float*)d_out;
    (void)in_sizes; (void)n_in; (void)out_size;

    pack_w_kernel<<<32, 256>>>(weight);
    xnor_v2_kernel<<<GRID, 128>>>(x, scale, out);
}

// round 12
// speedup vs baseline: 1.2962x; 1.2962x over previous
#include <cuda_runtime.h>
#include <stdint.h>

// XNOR binarized linear — R5 champion structure + streaming cache policy.
// y[n,o] = (256 - 2*popc(xbits[n] ^ wbits[o])) * scale[o]
//
// Every structural variant (occupancy 21-50%, instr count +/-40%, CSA popc,
// phase splits) pinned at ~3.18 TB/s achieved HBM. Hypothesis: L2 contention
// between the once-touched read stream and the write-allocated output stream.
// Fix: __ldcs on x (evict-first reads), __stcs on out (no-allocate writes).
// Everything else identical to the 140.8us champion.

constexpr int NROWS = 262144;
constexpr int DIM   = 256;   // IN == OUT
constexpr int WPR   = 8;     // packed words per row

constexpr int CHUNK_ROWS = 128;                 // rows per block (4 warps x 32)
constexpr int NBLOCKS    = NROWS / CHUNK_ROWS;  // 2048, one chunk per block

__device__ uint32_t g_wbits[DIM * WPR];

// ---------------------------------------------------------------------------
// Pre-kernel: pack weight sign bits (one warp per output row).
// Word (h*4+c), bit L  <->  element h*128 + 4L + c. Matches x packing below.
// ---------------------------------------------------------------------------
__global__ void pack_w_kernel(const float* __restrict__ w) {
    int warp = (blockIdx.x * blockDim.x + threadIdx.x) >> 5;
    int lane = threadIdx.x & 31;
    if (warp >= DIM) return;
    const float4* row = reinterpret_cast<const float4*>(w) + (size_t)warp * (DIM / 4);
#pragma unroll
    for (int h = 0; h < 2; ++h) {
        float4 v = row[h * 32 + lane];
        uint32_t m0 = __ballot_sync(0xFFFFFFFFu, v.x < 0.0f);
        uint32_t m1 = __ballot_sync(0xFFFFFFFFu, v.y < 0.0f);
        uint32_t m2 = __ballot_sync(0xFFFFFFFFu, v.z < 0.0f);
        uint32_t m3 = __ballot_sync(0xFFFFFFFFu, v.w < 0.0f);
        if (lane == 0) {
            *reinterpret_cast<uint4*>(&g_wbits[warp * WPR + h * 4]) =
                make_uint4(m0, m1, m2, m3);
        }
    }
}

// ---------------------------------------------------------------------------
// Main kernel: 128 threads (4 warps), one 128-row chunk per block.
// ---------------------------------------------------------------------------
__global__ void __launch_bounds__(128, 4)
xnor_stream_kernel(const float* __restrict__ x,
                   const float* __restrict__ scale,
                   float* __restrict__ out) {
    const int warp = threadIdx.x >> 5;
    const int lane = threadIdx.x & 31;

    // Hoist weights + scale for this lane's 8 output columns (strided o=32j+L).
    uint4 wlo[8], whi[8];
    float S[8];
#pragma unroll
    for (int j = 0; j < 8; ++j) {
        int o = j * 32 + lane;
        wlo[j] = *reinterpret_cast<const uint4*>(&g_wbits[o * WPR]);
        whi[j] = *reinterpret_cast<const uint4*>(&g_wbits[o * WPR + 4]);
        S[j] = scale[o];
    }

    constexpr uint32_t MAGIC256 = 0x4B400000u + 256u;   // 2^23*1.5 + 256

    const int row0 = blockIdx.x * CHUNK_ROWS + warp * 32;
    const float4* rp = reinterpret_cast<const float4*>(x) +
                       (size_t)row0 * (DIM / 4);
    float* orow = out + (size_t)row0 * DIM + lane;

    // prefetch first row (streaming loads: evict-first)
    float4 c0 = __ldcs(&rp[lane]);
    float4 c1 = __ldcs(&rp[32 + lane]);

#pragma unroll 2
    for (int r = 0; r < 32; ++r) {
        // prefetch next row (clamped on last iteration)
        const float4* np = rp + (size_t)(r + 1 < 32 ? r + 1 : r) * (DIM / 4);
        float4 n0 = __ldcs(&np[lane]);
        float4 n1 = __ldcs(&np[32 + lane]);

        // transpose row signs into 8 words, broadcast to all lanes
        uint32_t b0 = __ballot_sync(0xFFFFFFFFu, c0.x < 0.0f);
        uint32_t b1 = __ballot_sync(0xFFFFFFFFu, c0.y < 0.0f);
        uint32_t b2 = __ballot_sync(0xFFFFFFFFu, c0.z < 0.0f);
        uint32_t b3 = __ballot_sync(0xFFFFFFFFu, c0.w < 0.0f);
        uint32_t b4 = __ballot_sync(0xFFFFFFFFu, c1.x < 0.0f);
        uint32_t b5 = __ballot_sync(0xFFFFFFFFu, c1.y < 0.0f);
        uint32_t b6 = __ballot_sync(0xFFFFFFFFu, c1.z < 0.0f);
        uint32_t b7 = __ballot_sync(0xFFFFFFFFu, c1.w < 0.0f);

        // 8 independent output-group chains (ILP)
#pragma unroll
        for (int j = 0; j < 8; ++j) {
            int p = __popc(b0 ^ wlo[j].x) + __popc(b1 ^ wlo[j].y) +
                    __popc(b2 ^ wlo[j].z) + __popc(b3 ^ wlo[j].w) +
                    __popc(b4 ^ whi[j].x) + __popc(b5 ^ whi[j].y) +
                    __popc(b6 ^ whi[j].z) + __popc(b7 ^ whi[j].w);
            // exact: t = magic + (256-2p); fd = float(256-2p) exactly
            uint32_t t = MAGIC256 - 2u * (uint32_t)p;       // IMAD
            float fd = __uint_as_float(t) - 12582912.0f;    // FADD (exact)
            __stcs(&orow[j * 32], fd * S[j]);               // streaming STG
        }

        c0 = n0; c1 = n1;
        orow += DIM;
    }
}

// ---------------------------------------------------------------------------
// kernel_launch: d_in[0]=x [N,256] f32, d_in[1]=weight [256,256] f32,
//                d_in[2]=scale [1,256] f32; d_out = y [N,256] f32.
// ---------------------------------------------------------------------------
extern "C" void kernel_launch(void* const* d_in, const int* in_sizes, int n_in,
                              void* d_out, int out_size) {
    const float* x      = (const float*)d_in[0];
    const float* weight = (const float*)d_in[1];
    const float* scale  = (const float*)d_in[2];
    float* out          = (float*)d_out;
    (void)in_sizes; (void)n_in; (void)out_size;

    pack_w_kernel<<<32, 256>>>(weight);
    xnor_stream_kernel<<<NBLOCKS, 128>>>(x, scale, out);
}